// round 2
// baseline (speedup 1.0000x reference)
#include <cuda_runtime.h>
#include <math.h>

#define BB 8
#define TT 256
#define DD 12
#define HH 4
#define HD 3
#define NTOK (BB*TT)
#define DP 13   // padded row stride to dodge smem bank conflicts

// scratch for attention context (no cudaMalloc allowed)
__device__ float g_ctx[NTOK * DD];

// ---------------------------------------------------------------------------
// Kernel 1: fused QKV projection + per-head attention (online softmax).
// grid = B*H blocks, blockDim = T threads (one query per thread).
// ---------------------------------------------------------------------------
__global__ __launch_bounds__(TT)
void attn_kernel(const float* __restrict__ x,
                 const float* __restrict__ wq, const float* __restrict__ wk,
                 const float* __restrict__ wv,
                 const float* __restrict__ bq, const float* __restrict__ bk,
                 const float* __restrict__ bv)
{
    const int b = blockIdx.x >> 2;
    const int h = blockIdx.x & 3;
    const int t = threadIdx.x;

    __shared__ float xs[TT * DP];      // x[b] rows, padded
    __shared__ float ks[TT][HD];
    __shared__ float vs[TT][HD];

    // cooperative coalesced load of x[b] (256x12 floats)
    const float* xb = x + b * TT * DD;
    for (int i = t; i < TT * DD; i += TT) {
        int r = i / DD, c = i - r * DD;
        xs[r * DP + c] = xb[i];
    }
    __syncthreads();

    // per-token q/k/v for this head (weight reads broadcast within warp)
    float q[HD];
    {
        float k[HD], v[HD];
        #pragma unroll
        for (int i = 0; i < HD; i++) {
            const int r = h * HD + i;
            float aq = bq[r], ak = bk[r], av = bv[r];
            #pragma unroll
            for (int j = 0; j < DD; j++) {
                const float xj = xs[t * DP + j];
                aq += xj * wq[r * DD + j];
                ak += xj * wk[r * DD + j];
                av += xj * wv[r * DD + j];
            }
            q[i] = aq; k[i] = ak; v[i] = av;
        }
        #pragma unroll
        for (int i = 0; i < HD; i++) { ks[t][i] = k[i]; vs[t][i] = v[i]; }
    }
    __syncthreads();

    // online softmax over all 256 keys of this head
    const float scale = rsqrtf((float)HD);
    float m = -1e30f, l = 0.f, a0 = 0.f, a1 = 0.f, a2 = 0.f;
    #pragma unroll 4
    for (int s = 0; s < TT; s++) {
        const float k0 = ks[s][0], k1 = ks[s][1], k2 = ks[s][2];
        const float sc = (q[0]*k0 + q[1]*k1 + q[2]*k2) * scale;
        const float mn = fmaxf(m, sc);
        const float corr = __expf(m - mn);
        const float p = __expf(sc - mn);
        l  = l  * corr + p;
        a0 = a0 * corr + p * vs[s][0];
        a1 = a1 * corr + p * vs[s][1];
        a2 = a2 * corr + p * vs[s][2];
        m = mn;
    }
    const float inv = 1.0f / l;
    float* cp = g_ctx + (b * TT + t) * DD + h * HD;
    cp[0] = a0 * inv; cp[1] = a1 * inv; cp[2] = a2 * inv;
}

// ---------------------------------------------------------------------------
// Kernel 2: output projection + analytic quantum expectation values.
//   phi_w = (ctx @ wo.T + bo + theta)_w ;  c_w = cos(phi_w)
//   out[k] = prod_{j=0..k} c_j (k>=1) ;  out[0] = prod_{j=1..11} c_j
// grid = NTOK/128 blocks, 128 threads = one token per thread.
// ---------------------------------------------------------------------------
__global__ __launch_bounds__(128)
void proj_quantum_kernel(const float* __restrict__ wo,
                         const float* __restrict__ bo,
                         const float* __restrict__ theta,
                         float* __restrict__ out)
{
    const int tid = threadIdx.x;
    const int n0  = blockIdx.x * 128;     // first token of this block

    __shared__ float wos[DD * DD];
    __shared__ float bts[2 * DD];         // bo then theta
    __shared__ float buf[128 * DP];       // ctx in, results out (padded)

    for (int i = tid; i < DD * DD; i += 128) wos[i] = wo[i];   // 144 > 128: loop!
    if (tid < DD) { bts[tid] = bo[tid]; bts[DD + tid] = theta[tid]; }

    // coalesced load of 128 ctx rows
    for (int i = tid; i < 128 * DD; i += 128) {
        int r = i / DD, c = i - r * DD;
        buf[r * DP + c] = g_ctx[n0 * DD + i];
    }
    __syncthreads();

    float ctx[DD];
    #pragma unroll
    for (int j = 0; j < DD; j++) ctx[j] = buf[tid * DP + j];

    float c[DD];
    #pragma unroll
    for (int i = 0; i < DD; i++) {
        float a = bts[i];
        #pragma unroll
        for (int j = 0; j < DD; j++) a += ctx[j] * wos[i * DD + j];
        c[i] = cosf(a + bts[DD + i]);
    }

    float r[DD];
    float p = c[0];
    #pragma unroll
    for (int k = 1; k < DD; k++) { p *= c[k]; r[k] = p; }
    float s = 1.0f;
    #pragma unroll
    for (int j = 1; j < DD; j++) s *= c[j];
    r[0] = s;

    __syncthreads();
    #pragma unroll
    for (int i = 0; i < DD; i++) buf[tid * DP + i] = r[i];
    __syncthreads();

    // coalesced store
    for (int i = tid; i < 128 * DD; i += 128) {
        int rr = i / DD, cc = i - rr * DD;
        out[n0 * DD + i] = buf[rr * DP + cc];
    }
}

extern "C" void kernel_launch(void* const* d_in, const int* in_sizes, int n_in,
                              void* d_out, int out_size)
{
    const float* x     = (const float*)d_in[0];
    const float* wq    = (const float*)d_in[1];
    const float* wk    = (const float*)d_in[2];
    const float* wv    = (const float*)d_in[3];
    const float* bq    = (const float*)d_in[4];
    const float* bk    = (const float*)d_in[5];
    const float* bv    = (const float*)d_in[6];
    const float* wo    = (const float*)d_in[7];
    const float* bo    = (const float*)d_in[8];
    const float* theta = (const float*)d_in[9];
    float* out = (float*)d_out;

    attn_kernel<<<BB * HH, TT>>>(x, wq, wk, wv, bq, bk, bv);
    proj_quantum_kernel<<<NTOK / 128, 128>>>(wo, bo, theta, out);
}

// round 3
// speedup vs baseline: 2.0152x; 2.0152x over previous
#include <cuda_runtime.h>
#include <math.h>

#define BB 8
#define TT 256
#define DD 12
#define HH 4
#define HD 3
#define NTOK (BB*TT)

// scratch (no cudaMalloc allowed)
__device__ float g_q[NTOK * DD];          // [n][d] token-major
__device__ float g_kT[BB * HH * HD * TT]; // [b][h][i][t] key-major (coalesced)
__device__ float g_vT[BB * HH * HD * TT];
__device__ float g_ctx[NTOK * DD];

// ---------------------------------------------------------------------------
// K_A: QKV projection. One thread per (token, dim): 24576 threads.
// ---------------------------------------------------------------------------
__global__ __launch_bounds__(256)
void qkv_kernel(const float* __restrict__ x,
                const float* __restrict__ wq, const float* __restrict__ wk,
                const float* __restrict__ wv,
                const float* __restrict__ bq, const float* __restrict__ bk,
                const float* __restrict__ bv)
{
    const int u = blockIdx.x * 256 + threadIdx.x;   // 0 .. 24575
    const int n = u / DD;
    const int d = u - n * DD;

    const float* xr  = x  + n * DD;
    const float* wqr = wq + d * DD;
    const float* wkr = wk + d * DD;
    const float* wvr = wv + d * DD;

    float aq = bq[d], ak = bk[d], av = bv[d];
    #pragma unroll
    for (int j = 0; j < DD; j++) {
        const float xj = xr[j];
        aq += xj * wqr[j];
        ak += xj * wkr[j];
        av += xj * wvr[j];
    }
    g_q[u] = aq;

    const int b = n >> 8, t = n & 255;
    const int h = d / HD, i = d - h * HD;
    const int base = ((b * HH + h) * HD + i) * TT + t;
    g_kT[base] = ak;
    g_vT[base] = av;
}

// ---------------------------------------------------------------------------
// K_B: attention, one WARP per (b, h, query). 8192 warps total.
// Lane l handles keys l, l+32, ..., l+224 (8 keys). Warp-shfl reductions.
// ---------------------------------------------------------------------------
__global__ __launch_bounds__(128)
void attn_kernel(int dummy)
{
    const int wid  = threadIdx.x >> 5;
    const int lane = threadIdx.x & 31;
    const int g = blockIdx.x * 4 + wid;        // 0 .. 8191
    const int t = g & 255;
    const int h = (g >> 8) & 3;
    const int b = g >> 10;
    const int n = b * TT + t;

    const float* qp = g_q + n * DD + h * HD;   // broadcast within warp
    const float q0 = qp[0], q1 = qp[1], q2 = qp[2];

    const float* kb = g_kT + (b * HH + h) * HD * TT;
    const float* vb = g_vT + (b * HH + h) * HD * TT;
    const float scale = 0.57735026919f;        // 1/sqrt(3)

    float sc[8];
    float mx = -1e30f;
    #pragma unroll
    for (int m = 0; m < 8; m++) {
        const int s = lane + 32 * m;
        const float v = (q0 * kb[s] + q1 * kb[TT + s] + q2 * kb[2 * TT + s]) * scale;
        sc[m] = v;
        mx = fmaxf(mx, v);
    }
    #pragma unroll
    for (int off = 16; off > 0; off >>= 1)
        mx = fmaxf(mx, __shfl_xor_sync(0xFFFFFFFFu, mx, off));

    float l = 0.f, a0 = 0.f, a1 = 0.f, a2 = 0.f;
    #pragma unroll
    for (int m = 0; m < 8; m++) {
        const int s = lane + 32 * m;
        const float p = __expf(sc[m] - mx);
        l  += p;
        a0 += p * vb[s];
        a1 += p * vb[TT + s];
        a2 += p * vb[2 * TT + s];
    }
    #pragma unroll
    for (int off = 16; off > 0; off >>= 1) {
        l  += __shfl_xor_sync(0xFFFFFFFFu, l,  off);
        a0 += __shfl_xor_sync(0xFFFFFFFFu, a0, off);
        a1 += __shfl_xor_sync(0xFFFFFFFFu, a1, off);
        a2 += __shfl_xor_sync(0xFFFFFFFFu, a2, off);
    }
    if (lane == 0) {
        const float inv = 1.0f / l;
        float* cp = g_ctx + n * DD + h * HD;
        cp[0] = a0 * inv; cp[1] = a1 * inv; cp[2] = a2 * inv;
    }
}

// ---------------------------------------------------------------------------
// K_C: output projection + analytic quantum expvals.
// One thread per (token, wire): block = 32 tokens x 12 wires = 384 threads.
//   phi_w = (ctx @ wo.T + bo + theta)_w ; c_w = cos(phi_w)
//   out[k] = prod_{j=0..k} c_j (k>=1) ; out[0] = prod_{j=1..11} c_j
// ---------------------------------------------------------------------------
__global__ __launch_bounds__(384)
void proj_quantum_kernel(const float* __restrict__ wo,
                         const float* __restrict__ bo,
                         const float* __restrict__ theta,
                         float* __restrict__ out)
{
    const int tid = threadIdx.x;
    const int t = tid / DD;
    const int w = tid - t * DD;
    const int n0 = blockIdx.x * 32;

    __shared__ float wos[DD * DD];
    __shared__ float bts[2 * DD];
    __shared__ float ctxs[32][DD + 1];
    __shared__ float cs[32][DD + 1];

    if (tid < DD * DD) wos[tid] = wo[tid];
    if (tid < DD) { bts[tid] = bo[tid]; bts[DD + tid] = theta[tid]; }
    ctxs[t][w] = g_ctx[n0 * DD + tid];         // 384 = 32*12, one shot, coalesced
    __syncthreads();

    float a = bts[w] + bts[DD + w];
    #pragma unroll
    for (int j = 0; j < DD; j++) a += ctxs[t][j] * wos[w * DD + j];
    cs[t][w] = cosf(a);
    __syncthreads();

    float p;
    if (w == 0) {
        p = cs[t][1];
        #pragma unroll
        for (int j = 2; j < DD; j++) p *= cs[t][j];
    } else {
        p = cs[t][0];
        for (int j = 1; j <= w; j++) p *= cs[t][j];
    }
    out[(n0 + t) * DD + w] = p;                // coalesced
}

extern "C" void kernel_launch(void* const* d_in, const int* in_sizes, int n_in,
                              void* d_out, int out_size)
{
    const float* x     = (const float*)d_in[0];
    const float* wq    = (const float*)d_in[1];
    const float* wk    = (const float*)d_in[2];
    const float* wv    = (const float*)d_in[3];
    const float* bq    = (const float*)d_in[4];
    const float* bk    = (const float*)d_in[5];
    const float* bv    = (const float*)d_in[6];
    const float* wo    = (const float*)d_in[7];
    const float* bo    = (const float*)d_in[8];
    const float* theta = (const float*)d_in[9];
    float* out = (float*)d_out;

    qkv_kernel<<<NTOK * DD / 256, 256>>>(x, wq, wk, wv, bq, bk, bv);
    attn_kernel<<<NTOK * HH / 4, 128>>>(0);
    proj_quantum_kernel<<<NTOK / 32, 384>>>(wo, bo, theta, out);
}

// round 4
// speedup vs baseline: 2.3412x; 1.1618x over previous
#include <cuda_runtime.h>
#include <math.h>

#define BB 8
#define TT 256
#define DD 12
#define HH 4
#define HD 3
#define NTOK (BB*TT)

// scratch (no cudaMalloc allowed)
__device__ float g_q[NTOK * DD];          // [n][d] token-major
__device__ float g_kT[BB * HH * HD * TT]; // [b][h][i][t] key-major rows (float4-aligned)
__device__ float g_vT[BB * HH * HD * TT];

// ---------------------------------------------------------------------------
// K1: QKV projection, smem-staged. 16 tokens/block x 12 dims = 192 threads.
// ---------------------------------------------------------------------------
__global__ __launch_bounds__(192)
void qkv_kernel(const float* __restrict__ x,
                const float* __restrict__ wq, const float* __restrict__ wk,
                const float* __restrict__ wv,
                const float* __restrict__ bq, const float* __restrict__ bk,
                const float* __restrict__ bv)
{
    const int tid = threadIdx.x;
    const int n0  = blockIdx.x * 16;

    __shared__ float xs[16][DD + 1];
    __shared__ float wqs[DD * DD], wks[DD * DD], wvs[DD * DD];
    __shared__ float bs[3 * DD];

    if (tid < DD * DD) { wqs[tid] = wq[tid]; wks[tid] = wk[tid]; wvs[tid] = wv[tid]; }
    if (tid < DD) { bs[tid] = bq[tid]; bs[DD + tid] = bk[tid]; bs[2 * DD + tid] = bv[tid]; }
    {   // coalesced: 192 floats = 16 rows x 12
        const int r = tid / DD, c = tid - r * DD;
        xs[r][c] = x[n0 * DD + tid];
    }
    __syncthreads();

    const int t = tid / DD;
    const int d = tid - t * DD;
    const int n = n0 + t;

    float aq = bs[d], ak = bs[DD + d], av = bs[2 * DD + d];
    #pragma unroll
    for (int j = 0; j < DD; j++) {
        const float xj = xs[t][j];
        aq += xj * wqs[d * DD + j];
        ak += xj * wks[d * DD + j];
        av += xj * wvs[d * DD + j];
    }
    g_q[n * DD + d] = aq;                       // coalesced

    const int b = n >> 8, tt = n & 255;
    const int h = d / HD, i = d - h * HD;
    const int base = ((b * HH + h) * HD + i) * TT + tt;
    g_kT[base] = ak;
    g_vT[base] = av;
}

// ---------------------------------------------------------------------------
// K2: fused attention + output projection + analytic quantum expvals.
// Block = one token (128 thr). Warp h computes head h's ctx (float4 K/V reads,
// shfl reductions), then warp 0 finishes: phi = ctx@wo.T + bo + theta,
// c = cos(phi), out[k] = prod_{0..k} c (k>=1), out[0] = prod_{1..11} c.
// ---------------------------------------------------------------------------
__global__ __launch_bounds__(128)
void attn_quantum_kernel(const float* __restrict__ wo,
                         const float* __restrict__ bo,
                         const float* __restrict__ theta,
                         float* __restrict__ out)
{
    const int n    = blockIdx.x;
    const int h    = threadIdx.x >> 5;
    const int lane = threadIdx.x & 31;
    const int b    = n >> 8;

    __shared__ float ctxs[DD];
    __shared__ float cs[DD];

    // ---- attention: warp h handles head h of token n ----
    const float* qp = g_q + n * DD + h * HD;        // broadcast
    const float q0 = qp[0], q1 = qp[1], q2 = qp[2];

    const float4* kb4 = (const float4*)(g_kT + (b * HH + h) * HD * TT);
    const float4* vb4 = (const float4*)(g_vT + (b * HH + h) * HD * TT);
    // rows of 256 floats = 64 float4; key block A: f4 idx lane, B: 32+lane
    const float4 kxa = kb4[lane],       kxb = kb4[32 + lane];
    const float4 kya = kb4[64 + lane],  kyb = kb4[96 + lane];
    const float4 kza = kb4[128 + lane], kzb = kb4[160 + lane];
    const float4 vxa = vb4[lane],       vxb = vb4[32 + lane];
    const float4 vya = vb4[64 + lane],  vyb = vb4[96 + lane];
    const float4 vza = vb4[128 + lane], vzb = vb4[160 + lane];

    const float scale = 0.57735026919f;             // 1/sqrt(3)
    float sc[8];
    sc[0] = (q0*kxa.x + q1*kya.x + q2*kza.x) * scale;
    sc[1] = (q0*kxa.y + q1*kya.y + q2*kza.y) * scale;
    sc[2] = (q0*kxa.z + q1*kya.z + q2*kza.z) * scale;
    sc[3] = (q0*kxa.w + q1*kya.w + q2*kza.w) * scale;
    sc[4] = (q0*kxb.x + q1*kyb.x + q2*kzb.x) * scale;
    sc[5] = (q0*kxb.y + q1*kyb.y + q2*kzb.y) * scale;
    sc[6] = (q0*kxb.z + q1*kyb.z + q2*kzb.z) * scale;
    sc[7] = (q0*kxb.w + q1*kyb.w + q2*kzb.w) * scale;

    float mx = fmaxf(fmaxf(fmaxf(sc[0], sc[1]), fmaxf(sc[2], sc[3])),
                     fmaxf(fmaxf(sc[4], sc[5]), fmaxf(sc[6], sc[7])));
    #pragma unroll
    for (int off = 16; off > 0; off >>= 1)
        mx = fmaxf(mx, __shfl_xor_sync(0xFFFFFFFFu, mx, off));

    float p[8];
    #pragma unroll
    for (int m = 0; m < 8; m++) p[m] = __expf(sc[m] - mx);

    float l  = (p[0]+p[1]) + (p[2]+p[3]) + (p[4]+p[5]) + (p[6]+p[7]);
    float a0 = p[0]*vxa.x + p[1]*vxa.y + p[2]*vxa.z + p[3]*vxa.w
             + p[4]*vxb.x + p[5]*vxb.y + p[6]*vxb.z + p[7]*vxb.w;
    float a1 = p[0]*vya.x + p[1]*vya.y + p[2]*vya.z + p[3]*vya.w
             + p[4]*vyb.x + p[5]*vyb.y + p[6]*vyb.z + p[7]*vyb.w;
    float a2 = p[0]*vza.x + p[1]*vza.y + p[2]*vza.z + p[3]*vza.w
             + p[4]*vzb.x + p[5]*vzb.y + p[6]*vzb.z + p[7]*vzb.w;
    #pragma unroll
    for (int off = 16; off > 0; off >>= 1) {
        l  += __shfl_xor_sync(0xFFFFFFFFu, l,  off);
        a0 += __shfl_xor_sync(0xFFFFFFFFu, a0, off);
        a1 += __shfl_xor_sync(0xFFFFFFFFu, a1, off);
        a2 += __shfl_xor_sync(0xFFFFFFFFu, a2, off);
    }
    if (lane == 0) {
        const float inv = 1.0f / l;
        ctxs[h * HD + 0] = a0 * inv;
        ctxs[h * HD + 1] = a1 * inv;
        ctxs[h * HD + 2] = a2 * inv;
    }
    __syncthreads();

    // ---- projection + cos (threads 0..11) ----
    if (threadIdx.x < DD) {
        const int w = threadIdx.x;
        float a = __ldg(bo + w) + __ldg(theta + w);
        #pragma unroll
        for (int j = 0; j < DD; j++) a += ctxs[j] * __ldg(wo + w * DD + j);
        cs[w] = cosf(a);
    }
    __syncthreads();

    // ---- prefix products + store ----
    if (threadIdx.x < DD) {
        const int w = threadIdx.x;
        float r;
        if (w == 0) {
            r = cs[1];
            #pragma unroll
            for (int j = 2; j < DD; j++) r *= cs[j];
        } else {
            r = cs[0];
            for (int j = 1; j <= w; j++) r *= cs[j];
        }
        out[n * DD + w] = r;
    }
}

extern "C" void kernel_launch(void* const* d_in, const int* in_sizes, int n_in,
                              void* d_out, int out_size)
{
    const float* x     = (const float*)d_in[0];
    const float* wq    = (const float*)d_in[1];
    const float* wk    = (const float*)d_in[2];
    const float* wv    = (const float*)d_in[3];
    const float* bq    = (const float*)d_in[4];
    const float* bk    = (const float*)d_in[5];
    const float* bv    = (const float*)d_in[6];
    const float* wo    = (const float*)d_in[7];
    const float* bo    = (const float*)d_in[8];
    const float* theta = (const float*)d_in[9];
    float* out = (float*)d_out;

    qkv_kernel<<<NTOK / 16, 192>>>(x, wq, wk, wv, bq, bk, bv);
    attn_quantum_kernel<<<NTOK, 128>>>(wo, bo, theta, out);
}